// round 12
// baseline (speedup 1.0000x reference)
#include <cuda_runtime.h>
#include <cstdint>

#define SEQ   2048
#define EMB   768
#define NHEAD 12
#define HDIM  64
#define BH    24          // batch * heads
#define MTOT  4096        // batch * seq

// ---------------- scratch (allocation-free), all stored tf32-rounded ----------------
__device__ float g_Qs[(size_t)BH*SEQ*HDIM];   // Q * 0.125*log2e  [bh, n, d]
__device__ float g_Kc[(size_t)BH*SEQ*HDIM];   // K         [bh, n, d]
__device__ float g_Vt[(size_t)BH*HDIM*SEQ];   // V^T       [bh, d, n]
__device__ float g_AO[(size_t)MTOT*EMB];      // attention out [b, n, c] (tf32-rounded)
__device__ float g_X [(size_t)MTOT*EMB];      // x rounded to tf32
__device__ float g_Wq[(size_t)3*EMB*EMB];     // w_qkv rounded to tf32
__device__ float g_Wp[(size_t)EMB*EMB];       // w_proj rounded to tf32

// ---------------- helpers ----------------
__device__ __forceinline__ uint32_t f2tf(float x){
    uint32_t r; asm("cvt.rna.tf32.f32 %0, %1;" : "=r"(r) : "f"(x)); return r;
}
__device__ __forceinline__ float ex2(float x){           // MUFU.EX2 (2^x)
    float r; asm("ex2.approx.f32 %0, %1;" : "=f"(r) : "f"(x)); return r;
}
__device__ __forceinline__ void cp16(uint32_t dst, const void* src){
    asm volatile("cp.async.cg.shared.global [%0], [%1], 16;" :: "r"(dst), "l"(src));
}
__device__ __forceinline__ void cp_commit(){
    asm volatile("cp.async.commit_group;" ::: "memory");
}
template<int N>
__device__ __forceinline__ void cp_wait(){
    asm volatile("cp.async.wait_group %0;" :: "n"(N) : "memory");
}
__device__ __forceinline__ void mma_tf32(float* c, const uint32_t* a, const uint32_t* b){
    asm volatile(
        "mma.sync.aligned.m16n8k8.row.col.f32.tf32.tf32.f32 "
        "{%0,%1,%2,%3}, {%4,%5,%6,%7}, {%8,%9}, {%0,%1,%2,%3};"
        : "+f"(c[0]), "+f"(c[1]), "+f"(c[2]), "+f"(c[3])
        : "r"(a[0]), "r"(a[1]), "r"(a[2]), "r"(a[3]), "r"(b[0]), "r"(b[1]));
}

// ----------------------------------------------------------------------------
// Elementwise tf32 pre-round: out[i] = rna_tf32(in[i]). n % 1024 == 0.
// ----------------------------------------------------------------------------
__global__ void __launch_bounds__(256) round_kernel(
    const float* __restrict__ in, float* __restrict__ out, int n)
{
    int i = (blockIdx.x * 256 + threadIdx.x) * 4;
    if (i < n){
        float4 v = *(const float4*)(in + i);
        v.x = __uint_as_float(f2tf(v.x));
        v.y = __uint_as_float(f2tf(v.y));
        v.z = __uint_as_float(f2tf(v.z));
        v.w = __uint_as_float(f2tf(v.w));
        *(float4*)(out + i) = v;
    }
}

// ----------------------------------------------------------------------------
// tf32 mma.sync GEMM: D[128, 128] tile = A[M,K] @ B[N,K]^T + bias, BK=32.
// Single __syncthreads per k-iter.
//   MODE 0: QKV (A=g_X, B=g_Wq)    -> g_Qs(xscale)/g_Kc/g_Vt (V transposed)
//   MODE 3: proj (A=g_AO, B=g_Wp)  -> Cout + bias
// ----------------------------------------------------------------------------
template<int MODE>
__global__ void __launch_bounds__(256, 2) mm_kernel(
    const float* __restrict__ bias, float* __restrict__ Cout)
{
    constexpr int BN = 128, BK = 32, LDS = 36, NT = BN / 16;

    extern __shared__ float smg[];
    float* As = smg;                      // [2][128*36]
    float* Bs = smg + 2 * 128 * LDS;      // [2][128*36]

    const int tid  = threadIdx.x;
    const int wid  = tid >> 5, lane = tid & 31;
    const int lq   = lane >> 2, lr = lane & 3;
    const int mOff = (wid & 3) * 32;
    const int nOff = (wid >> 2) * (BN / 2);
    const int row0 = blockIdx.y * 128, col0 = blockIdx.x * BN;

    const float* Ap = (MODE == 0) ? g_X  : g_AO;
    const float* Bp = (MODE == 0) ? g_Wq : g_Wp;
    const int K = EMB;

    const uint32_t sA = (uint32_t)__cvta_generic_to_shared(As);
    const uint32_t sB = (uint32_t)__cvta_generic_to_shared(Bs);
    constexpr uint32_t BUFB = 128 * LDS * 4;   // bytes per buffer

    auto load_tile = [&](int kt, int buf){
        const float* ag = Ap + (size_t)row0 * K + kt * BK;
        const uint32_t da = sA + buf * BUFB;
        #pragma unroll
        for (int i = 0; i < 4; i++){              // 128x32 f = 1024 float4
            int ch = tid + i * 256, r = ch >> 3, c4 = ch & 7;
            cp16(da + (uint32_t)(r * LDS + c4 * 4) * 4, ag + (size_t)r * K + c4 * 4);
        }
        const float* bg = Bp + (size_t)col0 * K + kt * BK;
        const uint32_t db = sB + buf * BUFB;
        #pragma unroll
        for (int i = 0; i < 4; i++){
            int ch = tid + i * 256, r = ch >> 3, c4 = ch & 7;
            cp16(db + (uint32_t)(r * LDS + c4 * 4) * 4, bg + (size_t)r * K + c4 * 4);
        }
    };

    float acc[2][NT][4];
    #pragma unroll
    for (int mt = 0; mt < 2; mt++)
        #pragma unroll
        for (int nt = 0; nt < NT; nt++)
            #pragma unroll
            for (int j = 0; j < 4; j++) acc[mt][nt][j] = 0.f;

    load_tile(0, 0);
    cp_commit();

    const int KT = K / BK;                       // 24
    for (int kt = 0; kt < KT; kt++){
        cp_wait<0>();
        __syncthreads();                          // cp(kt) visible + buf^1 free
        if (kt + 1 < KT){ load_tile(kt + 1, (kt + 1) & 1); cp_commit(); }

        const float* a_s = As + (kt & 1) * 128 * LDS;
        const float* b_s = Bs + (kt & 1) * 128 * LDS;
        #pragma unroll
        for (int s = 0; s < 4; s++){
            const int k0 = s * 8;
            uint32_t af[2][4];
            #pragma unroll
            for (int mt = 0; mt < 2; mt++){
                const int r = mOff + mt * 16 + lq;
                af[mt][0] = __float_as_uint(a_s[(r    ) * LDS + k0 + lr    ]);
                af[mt][1] = __float_as_uint(a_s[(r + 8) * LDS + k0 + lr    ]);
                af[mt][2] = __float_as_uint(a_s[(r    ) * LDS + k0 + lr + 4]);
                af[mt][3] = __float_as_uint(a_s[(r + 8) * LDS + k0 + lr + 4]);
            }
            uint32_t bf[NT][2];
            #pragma unroll
            for (int nt = 0; nt < NT; nt++){
                const int c = nOff + nt * 8 + lq;
                bf[nt][0] = __float_as_uint(b_s[c * LDS + k0 + lr    ]);
                bf[nt][1] = __float_as_uint(b_s[c * LDS + k0 + lr + 4]);
            }
            #pragma unroll
            for (int mt = 0; mt < 2; mt++)
                #pragma unroll
                for (int nt = 0; nt < NT; nt++)
                    mma_tf32(acc[mt][nt], af[mt], bf[nt]);
        }
    }

    // ---------------- epilogue ----------------
    #pragma unroll
    for (int mt = 0; mt < 2; mt++){
        const int r1 = row0 + mOff + mt * 16 + lq;
        #pragma unroll
        for (int nt = 0; nt < NT; nt++){
            const int col = col0 + nOff + nt * 8 + lr * 2;
            #pragma unroll
            for (int half = 0; half < 2; half++){
                const int r = r1 + half * 8;
                const float v0 = acc[mt][nt][half * 2], v1 = acc[mt][nt][half * 2 + 1];
                if (MODE == 0){
                    const int part = col / EMB, cc = col - part * EMB;
                    const int h = cc >> 6, d = cc & 63;
                    const int bidx = r >> 11, n = r & (SEQ - 1);
                    if (part < 2){
                        // Q folded scale: 0.125 * log2(e) (softmax uses ex2)
                        const float sc = (part == 0) ? 0.18033688011112042f : 1.0f;
                        float* dst = (part == 0 ? g_Qs : g_Kc)
                                   + (((size_t)(bidx * NHEAD + h) * SEQ + n) * HDIM + d);
                        float2 w;
                        w.x = __uint_as_float(f2tf((v0 + bias[col    ]) * sc));
                        w.y = __uint_as_float(f2tf((v1 + bias[col + 1]) * sc));
                        *(float2*)dst = w;
                    } else {                     // V transposed: [bh, d, n]
                        const size_t vb = ((size_t)(bidx * NHEAD + h) * HDIM + d) * SEQ + n;
                        g_Vt[vb]       = __uint_as_float(f2tf(v0 + bias[col]));
                        g_Vt[vb + SEQ] = __uint_as_float(f2tf(v1 + bias[col + 1]));
                    }
                } else {
                    *(float2*)(Cout + (size_t)r * EMB + col)
                        = make_float2(v0 + bias[col], v1 + bias[col + 1]);
                }
            }
        }
    }
}

// ----------------------------------------------------------------------------
// Fused flash attention (R8 config): 4 warps x 32 query rows = 128 rows/CTA.
// S-phase nt-outer (K frags shared across both m16 tiles); LDP=68
// conflict-free; V^T tiles; 2 CTAs/SM. Softmax in exp2 domain via MUFU.EX2
// (scale*log2e folded into Q at QKV epilogue).
// ----------------------------------------------------------------------------
__global__ void __launch_bounds__(128, 2) attn_kernel()
{
    constexpr int TILE = 64, LDP = 68, NKT = SEQ / TILE;
    extern __shared__ float sm[];
    float* Ks = sm;                       // [2][64*68]  K tile [key][d]
    float* Vs = sm + 2 * TILE * LDP;      // [2][64*68]  V^T tile [d][key]
    float* Ps = sm + 4 * TILE * LDP;      // [128*68]    Q staging, then P

    const int tid  = threadIdx.x;
    const int wid  = tid >> 5, lane = tid & 31;
    const int lq   = lane >> 2, lr = lane & 3;
    const int z    = blockIdx.y;                 // head index (bh)
    const int row0 = blockIdx.x * 128;
    const size_t base  = (size_t)z * SEQ * HDIM;

    // ---- stage Q into Ps, extract persistent fragments (2 m16 tiles/warp) ----
    {
        const float* qg = g_Qs + base + (size_t)row0 * HDIM;
        #pragma unroll
        for (int i = 0; i < 16; i++){
            int ch = tid + i * 128, r = ch >> 4, c4 = ch & 15;
            *(float4*)&Ps[r * LDP + c4 * 4] = *(const float4*)(qg + r * HDIM + c4 * 4);
        }
    }
    __syncthreads();
    uint32_t qf[2][8][4];
    #pragma unroll
    for (int mt = 0; mt < 2; mt++){
        const int r = wid * 32 + mt * 16 + lq;
        #pragma unroll
        for (int ks = 0; ks < 8; ks++){
            qf[mt][ks][0] = __float_as_uint(Ps[(r    ) * LDP + ks * 8 + lr    ]);
            qf[mt][ks][1] = __float_as_uint(Ps[(r + 8) * LDP + ks * 8 + lr    ]);
            qf[mt][ks][2] = __float_as_uint(Ps[(r    ) * LDP + ks * 8 + lr + 4]);
            qf[mt][ks][3] = __float_as_uint(Ps[(r + 8) * LDP + ks * 8 + lr + 4]);
        }
    }

    float o[2][8][4];
    #pragma unroll
    for (int mt = 0; mt < 2; mt++)
        #pragma unroll
        for (int nt = 0; nt < 8; nt++)
            #pragma unroll
            for (int j = 0; j < 4; j++) o[mt][nt][j] = 0.f;
    float m_lo[2] = {-1e30f, -1e30f}, m_hi[2] = {-1e30f, -1e30f};
    float l_lo[2] = {0.f, 0.f},       l_hi[2] = {0.f, 0.f};

    auto load_kv = [&](int kt, int buf){
        const float* kg = g_Kc + base + (size_t)(kt * TILE) * HDIM;   // [key][d]
        const float* vg = g_Vt + base + (size_t)(kt * TILE);          // [d][n], col offset
        uint32_t kd = (uint32_t)__cvta_generic_to_shared(Ks + buf * TILE * LDP);
        uint32_t vd = (uint32_t)__cvta_generic_to_shared(Vs + buf * TILE * LDP);
        #pragma unroll
        for (int i = 0; i < 8; i++){              // 64x64 floats = 1024 float4
            int ch = tid + i * 128, r = ch >> 4, c4 = ch & 15;
            uint32_t off = (uint32_t)(r * LDP + c4 * 4) * 4;
            cp16(kd + off, kg + (size_t)r * HDIM + c4 * 4);
            cp16(vd + off, vg + (size_t)r * SEQ  + c4 * 4);
        }
    };

    load_kv(0, 0);
    cp_commit();

    for (int kt = 0; kt < NKT; kt++){
        const int buf = kt & 1;
        cp_wait<0>();
        __syncthreads();
        if (kt + 1 < NKT){ load_kv(kt + 1, buf ^ 1); cp_commit(); }

        const float* ks_ = Ks + buf * TILE * LDP;
        const float* vs_ = Vs + buf * TILE * LDP;

        // ---- S = Q @ K^T, nt-outer: K fragments shared across both m16 tiles ----
        float s[2][8][4];
        #pragma unroll
        for (int mt = 0; mt < 2; mt++)
            #pragma unroll
            for (int nt = 0; nt < 8; nt++)
                #pragma unroll
                for (int j = 0; j < 4; j++) s[mt][nt][j] = 0.f;
        #pragma unroll
        for (int nt = 0; nt < 8; nt++){
            uint32_t bfk[8][2];
            #pragma unroll
            for (int ks = 0; ks < 8; ks++){
                bfk[ks][0] = __float_as_uint(ks_[(nt * 8 + lq) * LDP + ks * 8 + lr    ]);
                bfk[ks][1] = __float_as_uint(ks_[(nt * 8 + lq) * LDP + ks * 8 + lr + 4]);
            }
            #pragma unroll
            for (int ks = 0; ks < 8; ks++){
                mma_tf32(s[0][nt], qf[0][ks], bfk[ks]);
                mma_tf32(s[1][nt], qf[1][ks], bfk[ks]);
            }
        }

        // ---- per m16 tile: online softmax (exp2 domain, MUFU.EX2), P -> smem ----
        #pragma unroll
        for (int mt = 0; mt < 2; mt++){
            float mx_lo = -1e30f, mx_hi = -1e30f;
            #pragma unroll
            for (int nt = 0; nt < 8; nt++){
                mx_lo = fmaxf(mx_lo, fmaxf(s[mt][nt][0], s[mt][nt][1]));
                mx_hi = fmaxf(mx_hi, fmaxf(s[mt][nt][2], s[mt][nt][3]));
            }
            mx_lo = fmaxf(mx_lo, __shfl_xor_sync(~0u, mx_lo, 1));
            mx_lo = fmaxf(mx_lo, __shfl_xor_sync(~0u, mx_lo, 2));
            mx_hi = fmaxf(mx_hi, __shfl_xor_sync(~0u, mx_hi, 1));
            mx_hi = fmaxf(mx_hi, __shfl_xor_sync(~0u, mx_hi, 2));
            const float mn_lo = fmaxf(m_lo[mt], mx_lo), mn_hi = fmaxf(m_hi[mt], mx_hi);
            const float c_lo = ex2(m_lo[mt] - mn_lo), c_hi = ex2(m_hi[mt] - mn_hi);
            float sum_lo = 0.f, sum_hi = 0.f;
            #pragma unroll
            for (int nt = 0; nt < 8; nt++){
                s[mt][nt][0] = ex2(s[mt][nt][0] - mn_lo);
                s[mt][nt][1] = ex2(s[mt][nt][1] - mn_lo);
                s[mt][nt][2] = ex2(s[mt][nt][2] - mn_hi);
                s[mt][nt][3] = ex2(s[mt][nt][3] - mn_hi);
                sum_lo += s[mt][nt][0] + s[mt][nt][1];
                sum_hi += s[mt][nt][2] + s[mt][nt][3];
            }
            sum_lo += __shfl_xor_sync(~0u, sum_lo, 1);
            sum_lo += __shfl_xor_sync(~0u, sum_lo, 2);
            sum_hi += __shfl_xor_sync(~0u, sum_hi, 1);
            sum_hi += __shfl_xor_sync(~0u, sum_hi, 2);
            l_lo[mt] = l_lo[mt] * c_lo + sum_lo;
            l_hi[mt] = l_hi[mt] * c_hi + sum_hi;
            #pragma unroll
            for (int nt = 0; nt < 8; nt++){
                o[mt][nt][0] *= c_lo; o[mt][nt][1] *= c_lo;
                o[mt][nt][2] *= c_hi; o[mt][nt][3] *= c_hi;
            }
            m_lo[mt] = mn_lo; m_hi[mt] = mn_hi;

            const int pr = wid * 32 + mt * 16 + lq;
            #pragma unroll
            for (int nt = 0; nt < 8; nt++){
                float2 w0, w1;
                w0.x = __uint_as_float(f2tf(s[mt][nt][0]));
                w0.y = __uint_as_float(f2tf(s[mt][nt][1]));
                w1.x = __uint_as_float(f2tf(s[mt][nt][2]));
                w1.y = __uint_as_float(f2tf(s[mt][nt][3]));
                *(float2*)&Ps[(pr    ) * LDP + nt * 8 + lr * 2] = w0;
                *(float2*)&Ps[(pr + 8) * LDP + nt * 8 + lr * 2] = w1;
            }
        }
        __syncwarp();

        // ---- O += P @ V  (V^T fragments, shared across both m16 tiles) ----
        const int pr0 = wid * 32 + lq, pr1 = pr0 + 16;
        #pragma unroll
        for (int ks = 0; ks < 8; ks++){
            uint32_t af0[4], af1[4];
            af0[0] = __float_as_uint(Ps[(pr0    ) * LDP + ks * 8 + lr    ]);
            af0[1] = __float_as_uint(Ps[(pr0 + 8) * LDP + ks * 8 + lr    ]);
            af0[2] = __float_as_uint(Ps[(pr0    ) * LDP + ks * 8 + lr + 4]);
            af0[3] = __float_as_uint(Ps[(pr0 + 8) * LDP + ks * 8 + lr + 4]);
            af1[0] = __float_as_uint(Ps[(pr1    ) * LDP + ks * 8 + lr    ]);
            af1[1] = __float_as_uint(Ps[(pr1 + 8) * LDP + ks * 8 + lr    ]);
            af1[2] = __float_as_uint(Ps[(pr1    ) * LDP + ks * 8 + lr + 4]);
            af1[3] = __float_as_uint(Ps[(pr1 + 8) * LDP + ks * 8 + lr + 4]);
            #pragma unroll
            for (int nt = 0; nt < 8; nt++){
                uint32_t bf2[2];
                bf2[0] = __float_as_uint(vs_[(nt * 8 + lq) * LDP + ks * 8 + lr    ]);
                bf2[1] = __float_as_uint(vs_[(nt * 8 + lq) * LDP + ks * 8 + lr + 4]);
                mma_tf32(o[0][nt], af0, bf2);
                mma_tf32(o[1][nt], af1, bf2);
            }
        }
        __syncwarp();
    }

    // ---- epilogue: tf32(O / l) -> g_AO[b, n, h*64 + d] ----
    const int bidx = z / NHEAD, h = z - bidx * NHEAD;
    #pragma unroll
    for (int mt = 0; mt < 2; mt++){
        const float inv_lo = 1.f / l_lo[mt], inv_hi = 1.f / l_hi[mt];
        const int r = row0 + wid * 32 + mt * 16 + lq;
        float* ob = g_AO + ((size_t)(bidx * SEQ + r)) * EMB + h * HDIM;
        #pragma unroll
        for (int nt = 0; nt < 8; nt++){
            const int col = nt * 8 + lr * 2;
            float2 w0, w1;
            w0.x = __uint_as_float(f2tf(o[mt][nt][0] * inv_lo));
            w0.y = __uint_as_float(f2tf(o[mt][nt][1] * inv_lo));
            w1.x = __uint_as_float(f2tf(o[mt][nt][2] * inv_hi));
            w1.y = __uint_as_float(f2tf(o[mt][nt][3] * inv_hi));
            *(float2*)(ob + col)           = w0;
            *(float2*)(ob + 8 * EMB + col) = w1;
        }
    }
}

// ----------------------------------------------------------------------------
extern "C" void kernel_launch(void* const* d_in, const int* in_sizes, int n_in,
                              void* d_out, int out_size)
{
    const float* x      = (const float*)d_in[0];
    const float* w_qkv  = (const float*)d_in[1];
    const float* b_qkv  = (const float*)d_in[2];
    const float* w_proj = (const float*)d_in[3];
    const float* b_proj = (const float*)d_in[4];
    float* out = (float*)d_out;

    constexpr int ASMEM  = (4 * 64 * 68 + 128 * 68) * 4;   // 104448 B
    constexpr int MMSMEM = 2 * 2 * 128 * 36 * 4;           // 73728 B
    cudaFuncSetAttribute(attn_kernel,  cudaFuncAttributeMaxDynamicSharedMemorySize, ASMEM);
    cudaFuncSetAttribute(mm_kernel<0>, cudaFuncAttributeMaxDynamicSharedMemorySize, MMSMEM);
    cudaFuncSetAttribute(mm_kernel<3>, cudaFuncAttributeMaxDynamicSharedMemorySize, MMSMEM);

    float* gX;  cudaGetSymbolAddress((void**)&gX,  g_X);
    float* gWq; cudaGetSymbolAddress((void**)&gWq, g_Wq);
    float* gWp; cudaGetSymbolAddress((void**)&gWp, g_Wp);

    // 0) pre-round inputs to tf32 (one-time, canonical RNA bits)
    round_kernel<<<(MTOT * EMB)     / 1024, 256>>>(x,      gX,  MTOT * EMB);
    round_kernel<<<(3 * EMB * EMB)  / 1024, 256>>>(w_qkv,  gWq, 3 * EMB * EMB);
    round_kernel<<<(EMB * EMB)      / 1024, 256>>>(w_proj, gWp, EMB * EMB);

    // 1) QKV GEMM + bias -> tf32-rounded Q(scaled, log2e folded)/K/V^T scratch
    mm_kernel<0><<<dim3(18, 32), 256, MMSMEM>>>(b_qkv, nullptr);
    // 2) fused flash attention -> g_AO (tf32-rounded)
    attn_kernel<<<dim3(SEQ / 128, BH), 128, ASMEM>>>();
    // 3) proj + bias -> out
    mm_kernel<3><<<dim3(6, 32), 256, MMSMEM>>>(b_proj, out);
}

// round 13
// speedup vs baseline: 1.1107x; 1.1107x over previous
#include <cuda_runtime.h>
#include <cstdint>

#define SEQ   2048
#define EMB   768
#define NHEAD 12
#define HDIM  64
#define BH    24          // batch * heads
#define MTOT  4096        // batch * seq

// ---------------- scratch (allocation-free), all stored tf32-rounded ----------------
__device__ float g_Qs[(size_t)BH*SEQ*HDIM];   // scaled Q  [bh, n, d]
__device__ float g_Kc[(size_t)BH*SEQ*HDIM];   // K         [bh, n, d]
__device__ float g_Vt[(size_t)BH*HDIM*SEQ];   // V^T       [bh, d, n]
__device__ float g_AO[(size_t)MTOT*EMB];      // attention out [b, n, c] (tf32-rounded)
__device__ float g_X [(size_t)MTOT*EMB];      // x rounded to tf32
__device__ float g_Wq[(size_t)3*EMB*EMB];     // w_qkv rounded to tf32
__device__ float g_Wp[(size_t)EMB*EMB];       // w_proj rounded to tf32

// ---------------- helpers ----------------
__device__ __forceinline__ uint32_t f2tf(float x){
    uint32_t r; asm("cvt.rna.tf32.f32 %0, %1;" : "=r"(r) : "f"(x)); return r;
}
__device__ __forceinline__ void cp16(uint32_t dst, const void* src){
    asm volatile("cp.async.cg.shared.global [%0], [%1], 16;" :: "r"(dst), "l"(src));
}
__device__ __forceinline__ void cp_commit(){
    asm volatile("cp.async.commit_group;" ::: "memory");
}
template<int N>
__device__ __forceinline__ void cp_wait(){
    asm volatile("cp.async.wait_group %0;" :: "n"(N) : "memory");
}
__device__ __forceinline__ void mma_tf32(float* c, const uint32_t* a, const uint32_t* b){
    asm volatile(
        "mma.sync.aligned.m16n8k8.row.col.f32.tf32.tf32.f32 "
        "{%0,%1,%2,%3}, {%4,%5,%6,%7}, {%8,%9}, {%0,%1,%2,%3};"
        : "+f"(c[0]), "+f"(c[1]), "+f"(c[2]), "+f"(c[3])
        : "r"(a[0]), "r"(a[1]), "r"(a[2]), "r"(a[3]), "r"(b[0]), "r"(b[1]));
}

// ----------------------------------------------------------------------------
// Elementwise tf32 pre-round: out[i] = rna_tf32(in[i]). n % 1024 == 0.
// ----------------------------------------------------------------------------
__global__ void __launch_bounds__(256) round_kernel(
    const float* __restrict__ in, float* __restrict__ out, int n)
{
    int i = (blockIdx.x * 256 + threadIdx.x) * 4;
    if (i < n){
        float4 v = *(const float4*)(in + i);
        v.x = __uint_as_float(f2tf(v.x));
        v.y = __uint_as_float(f2tf(v.y));
        v.z = __uint_as_float(f2tf(v.z));
        v.w = __uint_as_float(f2tf(v.w));
        *(float4*)(out + i) = v;
    }
}

// ----------------------------------------------------------------------------
// tf32 mma.sync GEMM: D[128, 128] tile = A[M,K] @ B[N,K]^T + bias, BK=48.
// 16 k-iters, 6 MMA-steps per barrier. LDS=52 -> conflict-free fragments.
//   MODE 0: QKV (A=g_X, B=g_Wq)    -> g_Qs(x0.125)/g_Kc/g_Vt (V transposed)
//   MODE 3: proj (A=g_AO, B=g_Wp)  -> Cout + bias
// ----------------------------------------------------------------------------
template<int MODE>
__global__ void __launch_bounds__(256, 2) mm_kernel(
    const float* __restrict__ bias, float* __restrict__ Cout)
{
    constexpr int BN = 128, BK = 48, LDS = 52, NT = BN / 16;

    extern __shared__ float smg[];
    float* As = smg;                      // [2][128*52]
    float* Bs = smg + 2 * 128 * LDS;      // [2][128*52]

    const int tid  = threadIdx.x;
    const int wid  = tid >> 5, lane = tid & 31;
    const int lq   = lane >> 2, lr = lane & 3;
    const int mOff = (wid & 3) * 32;
    const int nOff = (wid >> 2) * (BN / 2);
    const int row0 = blockIdx.y * 128, col0 = blockIdx.x * BN;

    const float* Ap = (MODE == 0) ? g_X  : g_AO;
    const float* Bp = (MODE == 0) ? g_Wq : g_Wp;
    const int K = EMB;

    const uint32_t sA = (uint32_t)__cvta_generic_to_shared(As);
    const uint32_t sB = (uint32_t)__cvta_generic_to_shared(Bs);
    constexpr uint32_t BUFB = 128 * LDS * 4;   // bytes per buffer

    auto load_tile = [&](int kt, int buf){
        const float* ag = Ap + (size_t)row0 * K + kt * BK;
        const uint32_t da = sA + buf * BUFB;
        #pragma unroll
        for (int i = 0; i < 6; i++){              // 128x48 f = 1536 float4
            int ch = tid + i * 256, r = ch / 12, c4 = ch % 12;
            cp16(da + (uint32_t)(r * LDS + c4 * 4) * 4, ag + (size_t)r * K + c4 * 4);
        }
        const float* bg = Bp + (size_t)col0 * K + kt * BK;
        const uint32_t db = sB + buf * BUFB;
        #pragma unroll
        for (int i = 0; i < 6; i++){
            int ch = tid + i * 256, r = ch / 12, c4 = ch % 12;
            cp16(db + (uint32_t)(r * LDS + c4 * 4) * 4, bg + (size_t)r * K + c4 * 4);
        }
    };

    float acc[2][NT][4];
    #pragma unroll
    for (int mt = 0; mt < 2; mt++)
        #pragma unroll
        for (int nt = 0; nt < NT; nt++)
            #pragma unroll
            for (int j = 0; j < 4; j++) acc[mt][nt][j] = 0.f;

    load_tile(0, 0);
    cp_commit();

    const int KT = K / BK;                       // 16
    for (int kt = 0; kt < KT; kt++){
        if (kt + 1 < KT){ load_tile(kt + 1, (kt + 1) & 1); cp_commit(); cp_wait<1>(); }
        else            { cp_wait<0>(); }
        __syncthreads();

        const float* a_s = As + (kt & 1) * 128 * LDS;
        const float* b_s = Bs + (kt & 1) * 128 * LDS;
        #pragma unroll
        for (int s = 0; s < 6; s++){
            const int k0 = s * 8;
            uint32_t af[2][4];
            #pragma unroll
            for (int mt = 0; mt < 2; mt++){
                const int r = mOff + mt * 16 + lq;
                af[mt][0] = __float_as_uint(a_s[(r    ) * LDS + k0 + lr    ]);
                af[mt][1] = __float_as_uint(a_s[(r + 8) * LDS + k0 + lr    ]);
                af[mt][2] = __float_as_uint(a_s[(r    ) * LDS + k0 + lr + 4]);
                af[mt][3] = __float_as_uint(a_s[(r + 8) * LDS + k0 + lr + 4]);
            }
            uint32_t bf[NT][2];
            #pragma unroll
            for (int nt = 0; nt < NT; nt++){
                const int c = nOff + nt * 8 + lq;
                bf[nt][0] = __float_as_uint(b_s[c * LDS + k0 + lr    ]);
                bf[nt][1] = __float_as_uint(b_s[c * LDS + k0 + lr + 4]);
            }
            #pragma unroll
            for (int mt = 0; mt < 2; mt++)
                #pragma unroll
                for (int nt = 0; nt < NT; nt++)
                    mma_tf32(acc[mt][nt], af[mt], bf[nt]);
        }
        __syncthreads();
    }

    // ---------------- epilogue ----------------
    #pragma unroll
    for (int mt = 0; mt < 2; mt++){
        const int r1 = row0 + mOff + mt * 16 + lq;
        #pragma unroll
        for (int nt = 0; nt < NT; nt++){
            const int col = col0 + nOff + nt * 8 + lr * 2;
            #pragma unroll
            for (int half = 0; half < 2; half++){
                const int r = r1 + half * 8;
                const float v0 = acc[mt][nt][half * 2], v1 = acc[mt][nt][half * 2 + 1];
                if (MODE == 0){
                    const int part = col / EMB, cc = col - part * EMB;
                    const int h = cc >> 6, d = cc & 63;
                    const int bidx = r >> 11, n = r & (SEQ - 1);
                    if (part < 2){
                        const float sc = (part == 0) ? 0.125f : 1.0f;
                        float* dst = (part == 0 ? g_Qs : g_Kc)
                                   + (((size_t)(bidx * NHEAD + h) * SEQ + n) * HDIM + d);
                        float2 w;
                        w.x = __uint_as_float(f2tf((v0 + bias[col    ]) * sc));
                        w.y = __uint_as_float(f2tf((v1 + bias[col + 1]) * sc));
                        *(float2*)dst = w;
                    } else {                     // V transposed: [bh, d, n]
                        const size_t vb = ((size_t)(bidx * NHEAD + h) * HDIM + d) * SEQ + n;
                        g_Vt[vb]       = __uint_as_float(f2tf(v0 + bias[col]));
                        g_Vt[vb + SEQ] = __uint_as_float(f2tf(v1 + bias[col + 1]));
                    }
                } else {
                    *(float2*)(Cout + (size_t)r * EMB + col)
                        = make_float2(v0 + bias[col], v1 + bias[col + 1]);
                }
            }
        }
    }
}

// ----------------------------------------------------------------------------
// Fused flash attention (R8 config, byte-identical): 4 warps x 32 query rows.
// S-phase nt-outer; LDP=68 conflict-free; V^T tiles; 2 CTAs/SM.
// ----------------------------------------------------------------------------
__global__ void __launch_bounds__(128, 2) attn_kernel()
{
    constexpr int TILE = 64, LDP = 68, NKT = SEQ / TILE;
    extern __shared__ float sm[];
    float* Ks = sm;                       // [2][64*68]  K tile [key][d]
    float* Vs = sm + 2 * TILE * LDP;      // [2][64*68]  V^T tile [d][key]
    float* Ps = sm + 4 * TILE * LDP;      // [128*68]    Q staging, then P

    const int tid  = threadIdx.x;
    const int wid  = tid >> 5, lane = tid & 31;
    const int lq   = lane >> 2, lr = lane & 3;
    const int z    = blockIdx.y;                 // head index (bh)
    const int row0 = blockIdx.x * 128;
    const size_t base  = (size_t)z * SEQ * HDIM;

    // ---- stage Q into Ps, extract persistent fragments (2 m16 tiles/warp) ----
    {
        const float* qg = g_Qs + base + (size_t)row0 * HDIM;
        #pragma unroll
        for (int i = 0; i < 16; i++){
            int ch = tid + i * 128, r = ch >> 4, c4 = ch & 15;
            *(float4*)&Ps[r * LDP + c4 * 4] = *(const float4*)(qg + r * HDIM + c4 * 4);
        }
    }
    __syncthreads();
    uint32_t qf[2][8][4];
    #pragma unroll
    for (int mt = 0; mt < 2; mt++){
        const int r = wid * 32 + mt * 16 + lq;
        #pragma unroll
        for (int ks = 0; ks < 8; ks++){
            qf[mt][ks][0] = __float_as_uint(Ps[(r    ) * LDP + ks * 8 + lr    ]);
            qf[mt][ks][1] = __float_as_uint(Ps[(r + 8) * LDP + ks * 8 + lr    ]);
            qf[mt][ks][2] = __float_as_uint(Ps[(r    ) * LDP + ks * 8 + lr + 4]);
            qf[mt][ks][3] = __float_as_uint(Ps[(r + 8) * LDP + ks * 8 + lr + 4]);
        }
    }

    float o[2][8][4];
    #pragma unroll
    for (int mt = 0; mt < 2; mt++)
        #pragma unroll
        for (int nt = 0; nt < 8; nt++)
            #pragma unroll
            for (int j = 0; j < 4; j++) o[mt][nt][j] = 0.f;
    float m_lo[2] = {-1e30f, -1e30f}, m_hi[2] = {-1e30f, -1e30f};
    float l_lo[2] = {0.f, 0.f},       l_hi[2] = {0.f, 0.f};

    auto load_kv = [&](int kt, int buf){
        const float* kg = g_Kc + base + (size_t)(kt * TILE) * HDIM;   // [key][d]
        const float* vg = g_Vt + base + (size_t)(kt * TILE);          // [d][n], col offset
        uint32_t kd = (uint32_t)__cvta_generic_to_shared(Ks + buf * TILE * LDP);
        uint32_t vd = (uint32_t)__cvta_generic_to_shared(Vs + buf * TILE * LDP);
        #pragma unroll
        for (int i = 0; i < 8; i++){              // 64x64 floats = 1024 float4
            int ch = tid + i * 128, r = ch >> 4, c4 = ch & 15;
            uint32_t off = (uint32_t)(r * LDP + c4 * 4) * 4;
            cp16(kd + off, kg + (size_t)r * HDIM + c4 * 4);
            cp16(vd + off, vg + (size_t)r * SEQ  + c4 * 4);
        }
    };

    load_kv(0, 0);
    cp_commit();

    for (int kt = 0; kt < NKT; kt++){
        const int buf = kt & 1;
        cp_wait<0>();
        __syncthreads();
        if (kt + 1 < NKT){ load_kv(kt + 1, buf ^ 1); cp_commit(); }

        const float* ks_ = Ks + buf * TILE * LDP;
        const float* vs_ = Vs + buf * TILE * LDP;

        // ---- S = Q @ K^T, nt-outer: K fragments shared across both m16 tiles ----
        float s[2][8][4];
        #pragma unroll
        for (int mt = 0; mt < 2; mt++)
            #pragma unroll
            for (int nt = 0; nt < 8; nt++)
                #pragma unroll
                for (int j = 0; j < 4; j++) s[mt][nt][j] = 0.f;
        #pragma unroll
        for (int nt = 0; nt < 8; nt++){
            uint32_t bfk[8][2];
            #pragma unroll
            for (int ks = 0; ks < 8; ks++){
                bfk[ks][0] = __float_as_uint(ks_[(nt * 8 + lq) * LDP + ks * 8 + lr    ]);
                bfk[ks][1] = __float_as_uint(ks_[(nt * 8 + lq) * LDP + ks * 8 + lr + 4]);
            }
            #pragma unroll
            for (int ks = 0; ks < 8; ks++){
                mma_tf32(s[0][nt], qf[0][ks], bfk[ks]);
                mma_tf32(s[1][nt], qf[1][ks], bfk[ks]);
            }
        }

        // ---- per m16 tile: online softmax, P -> smem ----
        #pragma unroll
        for (int mt = 0; mt < 2; mt++){
            float mx_lo = -1e30f, mx_hi = -1e30f;
            #pragma unroll
            for (int nt = 0; nt < 8; nt++){
                mx_lo = fmaxf(mx_lo, fmaxf(s[mt][nt][0], s[mt][nt][1]));
                mx_hi = fmaxf(mx_hi, fmaxf(s[mt][nt][2], s[mt][nt][3]));
            }
            mx_lo = fmaxf(mx_lo, __shfl_xor_sync(~0u, mx_lo, 1));
            mx_lo = fmaxf(mx_lo, __shfl_xor_sync(~0u, mx_lo, 2));
            mx_hi = fmaxf(mx_hi, __shfl_xor_sync(~0u, mx_hi, 1));
            mx_hi = fmaxf(mx_hi, __shfl_xor_sync(~0u, mx_hi, 2));
            const float mn_lo = fmaxf(m_lo[mt], mx_lo), mn_hi = fmaxf(m_hi[mt], mx_hi);
            const float c_lo = __expf(m_lo[mt] - mn_lo), c_hi = __expf(m_hi[mt] - mn_hi);
            float sum_lo = 0.f, sum_hi = 0.f;
            #pragma unroll
            for (int nt = 0; nt < 8; nt++){
                s[mt][nt][0] = __expf(s[mt][nt][0] - mn_lo);
                s[mt][nt][1] = __expf(s[mt][nt][1] - mn_lo);
                s[mt][nt][2] = __expf(s[mt][nt][2] - mn_hi);
                s[mt][nt][3] = __expf(s[mt][nt][3] - mn_hi);
                sum_lo += s[mt][nt][0] + s[mt][nt][1];
                sum_hi += s[mt][nt][2] + s[mt][nt][3];
            }
            sum_lo += __shfl_xor_sync(~0u, sum_lo, 1);
            sum_lo += __shfl_xor_sync(~0u, sum_lo, 2);
            sum_hi += __shfl_xor_sync(~0u, sum_hi, 1);
            sum_hi += __shfl_xor_sync(~0u, sum_hi, 2);
            l_lo[mt] = l_lo[mt] * c_lo + sum_lo;
            l_hi[mt] = l_hi[mt] * c_hi + sum_hi;
            #pragma unroll
            for (int nt = 0; nt < 8; nt++){
                o[mt][nt][0] *= c_lo; o[mt][nt][1] *= c_lo;
                o[mt][nt][2] *= c_hi; o[mt][nt][3] *= c_hi;
            }
            m_lo[mt] = mn_lo; m_hi[mt] = mn_hi;

            const int pr = wid * 32 + mt * 16 + lq;
            #pragma unroll
            for (int nt = 0; nt < 8; nt++){
                float2 w0, w1;
                w0.x = __uint_as_float(f2tf(s[mt][nt][0]));
                w0.y = __uint_as_float(f2tf(s[mt][nt][1]));
                w1.x = __uint_as_float(f2tf(s[mt][nt][2]));
                w1.y = __uint_as_float(f2tf(s[mt][nt][3]));
                *(float2*)&Ps[(pr    ) * LDP + nt * 8 + lr * 2] = w0;
                *(float2*)&Ps[(pr + 8) * LDP + nt * 8 + lr * 2] = w1;
            }
        }
        __syncwarp();

        // ---- O += P @ V  (V^T fragments, shared across both m16 tiles) ----
        const int pr0 = wid * 32 + lq, pr1 = pr0 + 16;
        #pragma unroll
        for (int ks = 0; ks < 8; ks++){
            uint32_t af0[4], af1[4];
            af0[0] = __float_as_uint(Ps[(pr0    ) * LDP + ks * 8 + lr    ]);
            af0[1] = __float_as_uint(Ps[(pr0 + 8) * LDP + ks * 8 + lr    ]);
            af0[2] = __float_as_uint(Ps[(pr0    ) * LDP + ks * 8 + lr + 4]);
            af0[3] = __float_as_uint(Ps[(pr0 + 8) * LDP + ks * 8 + lr + 4]);
            af1[0] = __float_as_uint(Ps[(pr1    ) * LDP + ks * 8 + lr    ]);
            af1[1] = __float_as_uint(Ps[(pr1 + 8) * LDP + ks * 8 + lr    ]);
            af1[2] = __float_as_uint(Ps[(pr1    ) * LDP + ks * 8 + lr + 4]);
            af1[3] = __float_as_uint(Ps[(pr1 + 8) * LDP + ks * 8 + lr + 4]);
            #pragma unroll
            for (int nt = 0; nt < 8; nt++){
                uint32_t bf2[2];
                bf2[0] = __float_as_uint(vs_[(nt * 8 + lq) * LDP + ks * 8 + lr    ]);
                bf2[1] = __float_as_uint(vs_[(nt * 8 + lq) * LDP + ks * 8 + lr + 4]);
                mma_tf32(o[0][nt], af0, bf2);
                mma_tf32(o[1][nt], af1, bf2);
            }
        }
        __syncwarp();
    }

    // ---- epilogue: tf32(O / l) -> g_AO[b, n, h*64 + d] ----
    const int bidx = z / NHEAD, h = z - bidx * NHEAD;
    #pragma unroll
    for (int mt = 0; mt < 2; mt++){
        const float inv_lo = 1.f / l_lo[mt], inv_hi = 1.f / l_hi[mt];
        const int r = row0 + wid * 32 + mt * 16 + lq;
        float* ob = g_AO + ((size_t)(bidx * SEQ + r)) * EMB + h * HDIM;
        #pragma unroll
        for (int nt = 0; nt < 8; nt++){
            const int col = nt * 8 + lr * 2;
            float2 w0, w1;
            w0.x = __uint_as_float(f2tf(o[mt][nt][0] * inv_lo));
            w0.y = __uint_as_float(f2tf(o[mt][nt][1] * inv_lo));
            w1.x = __uint_as_float(f2tf(o[mt][nt][2] * inv_hi));
            w1.y = __uint_as_float(f2tf(o[mt][nt][3] * inv_hi));
            *(float2*)(ob + col)           = w0;
            *(float2*)(ob + 8 * EMB + col) = w1;
        }
    }
}

// ----------------------------------------------------------------------------
extern "C" void kernel_launch(void* const* d_in, const int* in_sizes, int n_in,
                              void* d_out, int out_size)
{
    const float* x      = (const float*)d_in[0];
    const float* w_qkv  = (const float*)d_in[1];
    const float* b_qkv  = (const float*)d_in[2];
    const float* w_proj = (const float*)d_in[3];
    const float* b_proj = (const float*)d_in[4];
    float* out = (float*)d_out;

    constexpr int ASMEM  = (4 * 64 * 68 + 128 * 68) * 4;   // 104448 B
    constexpr int MMSMEM = 2 * 2 * 128 * 52 * 4;           // 106496 B
    cudaFuncSetAttribute(attn_kernel,  cudaFuncAttributeMaxDynamicSharedMemorySize, ASMEM);
    cudaFuncSetAttribute(mm_kernel<0>, cudaFuncAttributeMaxDynamicSharedMemorySize, MMSMEM);
    cudaFuncSetAttribute(mm_kernel<3>, cudaFuncAttributeMaxDynamicSharedMemorySize, MMSMEM);

    float* gX;  cudaGetSymbolAddress((void**)&gX,  g_X);
    float* gWq; cudaGetSymbolAddress((void**)&gWq, g_Wq);
    float* gWp; cudaGetSymbolAddress((void**)&gWp, g_Wp);

    // 0) pre-round inputs to tf32 (one-time, canonical RNA bits)
    round_kernel<<<(MTOT * EMB)     / 1024, 256>>>(x,      gX,  MTOT * EMB);
    round_kernel<<<(3 * EMB * EMB)  / 1024, 256>>>(w_qkv,  gWq, 3 * EMB * EMB);
    round_kernel<<<(EMB * EMB)      / 1024, 256>>>(w_proj, gWp, EMB * EMB);

    // 1) QKV GEMM + bias -> tf32-rounded Q(scaled)/K/V^T scratch
    mm_kernel<0><<<dim3(18, 32), 256, MMSMEM>>>(b_qkv, nullptr);
    // 2) fused flash attention -> g_AO (tf32-rounded)
    attn_kernel<<<dim3(SEQ / 128, BH), 128, ASMEM>>>();
    // 3) proj + bias -> out
    mm_kernel<3><<<dim3(6, 32), 256, MMSMEM>>>(b_proj, out);
}

// round 14
// speedup vs baseline: 1.1451x; 1.0310x over previous
#include <cuda_runtime.h>
#include <cstdint>

#define SEQ   2048
#define EMB   768
#define NHEAD 12
#define HDIM  64
#define BH    24          // batch * heads
#define MTOT  4096        // batch * seq

// ---------------- scratch (allocation-free), all stored tf32-rounded ----------------
__device__ float g_Qs[(size_t)BH*SEQ*HDIM];   // scaled Q  [bh, n, d]
__device__ float g_Kc[(size_t)BH*SEQ*HDIM];   // K         [bh, n, d]
__device__ float g_Vt[(size_t)BH*HDIM*SEQ];   // V^T       [bh, d, n]
__device__ float g_AO[(size_t)MTOT*EMB];      // attention out [b, n, c] (tf32-rounded)
__device__ float g_X [(size_t)MTOT*EMB];      // x rounded to tf32
__device__ float g_Wq[(size_t)3*EMB*EMB];     // w_qkv rounded to tf32
__device__ float g_Wp[(size_t)EMB*EMB];       // w_proj rounded to tf32

// ---------------- helpers ----------------
__device__ __forceinline__ uint32_t f2tf(float x){
    uint32_t r; asm("cvt.rna.tf32.f32 %0, %1;" : "=r"(r) : "f"(x)); return r;
}
__device__ __forceinline__ void cp16(uint32_t dst, const void* src){
    asm volatile("cp.async.cg.shared.global [%0], [%1], 16;" :: "r"(dst), "l"(src));
}
__device__ __forceinline__ void cp_commit(){
    asm volatile("cp.async.commit_group;" ::: "memory");
}
template<int N>
__device__ __forceinline__ void cp_wait(){
    asm volatile("cp.async.wait_group %0;" :: "n"(N) : "memory");
}
__device__ __forceinline__ void mma_tf32(float* c, const uint32_t* a, const uint32_t* b){
    asm volatile(
        "mma.sync.aligned.m16n8k8.row.col.f32.tf32.tf32.f32 "
        "{%0,%1,%2,%3}, {%4,%5,%6,%7}, {%8,%9}, {%0,%1,%2,%3};"
        : "+f"(c[0]), "+f"(c[1]), "+f"(c[2]), "+f"(c[3])
        : "r"(a[0]), "r"(a[1]), "r"(a[2]), "r"(a[3]), "r"(b[0]), "r"(b[1]));
}

// ----------------------------------------------------------------------------
// Fused tf32 pre-round of all three inputs in ONE launch.
// Quad ranges: [0,Q1) -> x, [Q1,Q1+Q2) -> w_qkv, [Q1+Q2,Q1+Q2+Q3) -> w_proj.
// ----------------------------------------------------------------------------
#define Q1 (MTOT*EMB/4)
#define Q2 (3*EMB*EMB/4)
#define Q3 (EMB*EMB/4)
__global__ void __launch_bounds__(256) round_all_kernel(
    const float* __restrict__ x, const float* __restrict__ wq,
    const float* __restrict__ wp)
{
    int q = blockIdx.x * 256 + threadIdx.x;
    const float* src; float* dst; int off;
    if (q < Q1)           { src = x;  dst = g_X;  off = q; }
    else if (q < Q1 + Q2) { src = wq; dst = g_Wq; off = q - Q1; }
    else if (q < Q1 + Q2 + Q3) { src = wp; dst = g_Wp; off = q - Q1 - Q2; }
    else return;
    int i = off * 4;
    float4 v = *(const float4*)(src + i);
    v.x = __uint_as_float(f2tf(v.x));
    v.y = __uint_as_float(f2tf(v.y));
    v.z = __uint_as_float(f2tf(v.z));
    v.w = __uint_as_float(f2tf(v.w));
    *(float4*)(dst + i) = v;
}

// ----------------------------------------------------------------------------
// tf32 mma.sync GEMM: D[128, 128] tile = A[M,K] @ B[N,K]^T + bias, BK=32.
// Single __syncthreads per k-iter (wait<0>+sync covers cp-visibility AND
// buffer-reuse; verified correct R11/R12).
//   MODE 0: QKV (A=g_X, B=g_Wq)    -> g_Qs(x0.125)/g_Kc/g_Vt (V transposed)
//   MODE 3: proj (A=g_AO, B=g_Wp)  -> Cout + bias
// ----------------------------------------------------------------------------
template<int MODE>
__global__ void __launch_bounds__(256, 2) mm_kernel(
    const float* __restrict__ bias, float* __restrict__ Cout)
{
    constexpr int BN = 128, BK = 32, LDS = 36, NT = BN / 16;

    extern __shared__ float smg[];
    float* As = smg;                      // [2][128*36]
    float* Bs = smg + 2 * 128 * LDS;      // [2][128*36]

    const int tid  = threadIdx.x;
    const int wid  = tid >> 5, lane = tid & 31;
    const int lq   = lane >> 2, lr = lane & 3;
    const int mOff = (wid & 3) * 32;
    const int nOff = (wid >> 2) * (BN / 2);
    const int row0 = blockIdx.y * 128, col0 = blockIdx.x * BN;

    const float* Ap = (MODE == 0) ? g_X  : g_AO;
    const float* Bp = (MODE == 0) ? g_Wq : g_Wp;
    const int K = EMB;

    const uint32_t sA = (uint32_t)__cvta_generic_to_shared(As);
    const uint32_t sB = (uint32_t)__cvta_generic_to_shared(Bs);
    constexpr uint32_t BUFB = 128 * LDS * 4;   // bytes per buffer

    auto load_tile = [&](int kt, int buf){
        const float* ag = Ap + (size_t)row0 * K + kt * BK;
        const uint32_t da = sA + buf * BUFB;
        #pragma unroll
        for (int i = 0; i < 4; i++){              // 128x32 f = 1024 float4
            int ch = tid + i * 256, r = ch >> 3, c4 = ch & 7;
            cp16(da + (uint32_t)(r * LDS + c4 * 4) * 4, ag + (size_t)r * K + c4 * 4);
        }
        const float* bg = Bp + (size_t)col0 * K + kt * BK;
        const uint32_t db = sB + buf * BUFB;
        #pragma unroll
        for (int i = 0; i < 4; i++){
            int ch = tid + i * 256, r = ch >> 3, c4 = ch & 7;
            cp16(db + (uint32_t)(r * LDS + c4 * 4) * 4, bg + (size_t)r * K + c4 * 4);
        }
    };

    float acc[2][NT][4];
    #pragma unroll
    for (int mt = 0; mt < 2; mt++)
        #pragma unroll
        for (int nt = 0; nt < NT; nt++)
            #pragma unroll
            for (int j = 0; j < 4; j++) acc[mt][nt][j] = 0.f;

    load_tile(0, 0);
    cp_commit();

    const int KT = K / BK;                       // 24
    for (int kt = 0; kt < KT; kt++){
        cp_wait<0>();
        __syncthreads();                          // cp(kt) visible + buf^1 free
        if (kt + 1 < KT){ load_tile(kt + 1, (kt + 1) & 1); cp_commit(); }

        const float* a_s = As + (kt & 1) * 128 * LDS;
        const float* b_s = Bs + (kt & 1) * 128 * LDS;
        #pragma unroll
        for (int s = 0; s < 4; s++){
            const int k0 = s * 8;
            uint32_t af[2][4];
            #pragma unroll
            for (int mt = 0; mt < 2; mt++){
                const int r = mOff + mt * 16 + lq;
                af[mt][0] = __float_as_uint(a_s[(r    ) * LDS + k0 + lr    ]);
                af[mt][1] = __float_as_uint(a_s[(r + 8) * LDS + k0 + lr    ]);
                af[mt][2] = __float_as_uint(a_s[(r    ) * LDS + k0 + lr + 4]);
                af[mt][3] = __float_as_uint(a_s[(r + 8) * LDS + k0 + lr + 4]);
            }
            uint32_t bf[NT][2];
            #pragma unroll
            for (int nt = 0; nt < NT; nt++){
                const int c = nOff + nt * 8 + lq;
                bf[nt][0] = __float_as_uint(b_s[c * LDS + k0 + lr    ]);
                bf[nt][1] = __float_as_uint(b_s[c * LDS + k0 + lr + 4]);
            }
            #pragma unroll
            for (int mt = 0; mt < 2; mt++)
                #pragma unroll
                for (int nt = 0; nt < NT; nt++)
                    mma_tf32(acc[mt][nt], af[mt], bf[nt]);
        }
    }

    // ---------------- epilogue ----------------
    #pragma unroll
    for (int mt = 0; mt < 2; mt++){
        const int r1 = row0 + mOff + mt * 16 + lq;
        #pragma unroll
        for (int nt = 0; nt < NT; nt++){
            const int col = col0 + nOff + nt * 8 + lr * 2;
            #pragma unroll
            for (int half = 0; half < 2; half++){
                const int r = r1 + half * 8;
                const float v0 = acc[mt][nt][half * 2], v1 = acc[mt][nt][half * 2 + 1];
                if (MODE == 0){
                    const int part = col / EMB, cc = col - part * EMB;
                    const int h = cc >> 6, d = cc & 63;
                    const int bidx = r >> 11, n = r & (SEQ - 1);
                    if (part < 2){
                        const float sc = (part == 0) ? 0.125f : 1.0f;
                        float* dst = (part == 0 ? g_Qs : g_Kc)
                                   + (((size_t)(bidx * NHEAD + h) * SEQ + n) * HDIM + d);
                        float2 w;
                        w.x = __uint_as_float(f2tf((v0 + bias[col    ]) * sc));
                        w.y = __uint_as_float(f2tf((v1 + bias[col + 1]) * sc));
                        *(float2*)dst = w;
                    } else {                     // V transposed: [bh, d, n]
                        const size_t vb = ((size_t)(bidx * NHEAD + h) * HDIM + d) * SEQ + n;
                        g_Vt[vb]       = __uint_as_float(f2tf(v0 + bias[col]));
                        g_Vt[vb + SEQ] = __uint_as_float(f2tf(v1 + bias[col + 1]));
                    }
                } else {
                    *(float2*)(Cout + (size_t)r * EMB + col)
                        = make_float2(v0 + bias[col], v1 + bias[col + 1]);
                }
            }
        }
    }
}

// ----------------------------------------------------------------------------
// Fused flash attention (R8 champion config, byte-identical):
// 4 warps x 32 query rows = 128 rows/CTA; S-phase nt-outer (K frags shared
// across both m16 tiles); LDP=68 conflict-free; V^T tiles; 2 CTAs/SM.
// ----------------------------------------------------------------------------
__global__ void __launch_bounds__(128, 2) attn_kernel()
{
    constexpr int TILE = 64, LDP = 68, NKT = SEQ / TILE;
    extern __shared__ float sm[];
    float* Ks = sm;                       // [2][64*68]  K tile [key][d]
    float* Vs = sm + 2 * TILE * LDP;      // [2][64*68]  V^T tile [d][key]
    float* Ps = sm + 4 * TILE * LDP;      // [128*68]    Q staging, then P

    const int tid  = threadIdx.x;
    const int wid  = tid >> 5, lane = tid & 31;
    const int lq   = lane >> 2, lr = lane & 3;
    const int z    = blockIdx.y;                 // head index (bh)
    const int row0 = blockIdx.x * 128;
    const size_t base  = (size_t)z * SEQ * HDIM;

    // ---- stage Q into Ps, extract persistent fragments (2 m16 tiles/warp) ----
    {
        const float* qg = g_Qs + base + (size_t)row0 * HDIM;
        #pragma unroll
        for (int i = 0; i < 16; i++){
            int ch = tid + i * 128, r = ch >> 4, c4 = ch & 15;
            *(float4*)&Ps[r * LDP + c4 * 4] = *(const float4*)(qg + r * HDIM + c4 * 4);
        }
    }
    __syncthreads();
    uint32_t qf[2][8][4];
    #pragma unroll
    for (int mt = 0; mt < 2; mt++){
        const int r = wid * 32 + mt * 16 + lq;
        #pragma unroll
        for (int ks = 0; ks < 8; ks++){
            qf[mt][ks][0] = __float_as_uint(Ps[(r    ) * LDP + ks * 8 + lr    ]);
            qf[mt][ks][1] = __float_as_uint(Ps[(r + 8) * LDP + ks * 8 + lr    ]);
            qf[mt][ks][2] = __float_as_uint(Ps[(r    ) * LDP + ks * 8 + lr + 4]);
            qf[mt][ks][3] = __float_as_uint(Ps[(r + 8) * LDP + ks * 8 + lr + 4]);
        }
    }

    float o[2][8][4];
    #pragma unroll
    for (int mt = 0; mt < 2; mt++)
        #pragma unroll
        for (int nt = 0; nt < 8; nt++)
            #pragma unroll
            for (int j = 0; j < 4; j++) o[mt][nt][j] = 0.f;
    float m_lo[2] = {-1e30f, -1e30f}, m_hi[2] = {-1e30f, -1e30f};
    float l_lo[2] = {0.f, 0.f},       l_hi[2] = {0.f, 0.f};

    auto load_kv = [&](int kt, int buf){
        const float* kg = g_Kc + base + (size_t)(kt * TILE) * HDIM;   // [key][d]
        const float* vg = g_Vt + base + (size_t)(kt * TILE);          // [d][n], col offset
        uint32_t kd = (uint32_t)__cvta_generic_to_shared(Ks + buf * TILE * LDP);
        uint32_t vd = (uint32_t)__cvta_generic_to_shared(Vs + buf * TILE * LDP);
        #pragma unroll
        for (int i = 0; i < 8; i++){              // 64x64 floats = 1024 float4
            int ch = tid + i * 128, r = ch >> 4, c4 = ch & 15;
            uint32_t off = (uint32_t)(r * LDP + c4 * 4) * 4;
            cp16(kd + off, kg + (size_t)r * HDIM + c4 * 4);
            cp16(vd + off, vg + (size_t)r * SEQ  + c4 * 4);
        }
    };

    load_kv(0, 0);
    cp_commit();

    for (int kt = 0; kt < NKT; kt++){
        const int buf = kt & 1;
        cp_wait<0>();
        __syncthreads();
        if (kt + 1 < NKT){ load_kv(kt + 1, buf ^ 1); cp_commit(); }

        const float* ks_ = Ks + buf * TILE * LDP;
        const float* vs_ = Vs + buf * TILE * LDP;

        // ---- S = Q @ K^T, nt-outer: K fragments shared across both m16 tiles ----
        float s[2][8][4];
        #pragma unroll
        for (int mt = 0; mt < 2; mt++)
            #pragma unroll
            for (int nt = 0; nt < 8; nt++)
                #pragma unroll
                for (int j = 0; j < 4; j++) s[mt][nt][j] = 0.f;
        #pragma unroll
        for (int nt = 0; nt < 8; nt++){
            uint32_t bfk[8][2];
            #pragma unroll
            for (int ks = 0; ks < 8; ks++){
                bfk[ks][0] = __float_as_uint(ks_[(nt * 8 + lq) * LDP + ks * 8 + lr    ]);
                bfk[ks][1] = __float_as_uint(ks_[(nt * 8 + lq) * LDP + ks * 8 + lr + 4]);
            }
            #pragma unroll
            for (int ks = 0; ks < 8; ks++){
                mma_tf32(s[0][nt], qf[0][ks], bfk[ks]);
                mma_tf32(s[1][nt], qf[1][ks], bfk[ks]);
            }
        }

        // ---- per m16 tile: online softmax, P -> smem ----
        #pragma unroll
        for (int mt = 0; mt < 2; mt++){
            float mx_lo = -1e30f, mx_hi = -1e30f;
            #pragma unroll
            for (int nt = 0; nt < 8; nt++){
                mx_lo = fmaxf(mx_lo, fmaxf(s[mt][nt][0], s[mt][nt][1]));
                mx_hi = fmaxf(mx_hi, fmaxf(s[mt][nt][2], s[mt][nt][3]));
            }
            mx_lo = fmaxf(mx_lo, __shfl_xor_sync(~0u, mx_lo, 1));
            mx_lo = fmaxf(mx_lo, __shfl_xor_sync(~0u, mx_lo, 2));
            mx_hi = fmaxf(mx_hi, __shfl_xor_sync(~0u, mx_hi, 1));
            mx_hi = fmaxf(mx_hi, __shfl_xor_sync(~0u, mx_hi, 2));
            const float mn_lo = fmaxf(m_lo[mt], mx_lo), mn_hi = fmaxf(m_hi[mt], mx_hi);
            const float c_lo = __expf(m_lo[mt] - mn_lo), c_hi = __expf(m_hi[mt] - mn_hi);
            float sum_lo = 0.f, sum_hi = 0.f;
            #pragma unroll
            for (int nt = 0; nt < 8; nt++){
                s[mt][nt][0] = __expf(s[mt][nt][0] - mn_lo);
                s[mt][nt][1] = __expf(s[mt][nt][1] - mn_lo);
                s[mt][nt][2] = __expf(s[mt][nt][2] - mn_hi);
                s[mt][nt][3] = __expf(s[mt][nt][3] - mn_hi);
                sum_lo += s[mt][nt][0] + s[mt][nt][1];
                sum_hi += s[mt][nt][2] + s[mt][nt][3];
            }
            sum_lo += __shfl_xor_sync(~0u, sum_lo, 1);
            sum_lo += __shfl_xor_sync(~0u, sum_lo, 2);
            sum_hi += __shfl_xor_sync(~0u, sum_hi, 1);
            sum_hi += __shfl_xor_sync(~0u, sum_hi, 2);
            l_lo[mt] = l_lo[mt] * c_lo + sum_lo;
            l_hi[mt] = l_hi[mt] * c_hi + sum_hi;
            #pragma unroll
            for (int nt = 0; nt < 8; nt++){
                o[mt][nt][0] *= c_lo; o[mt][nt][1] *= c_lo;
                o[mt][nt][2] *= c_hi; o[mt][nt][3] *= c_hi;
            }
            m_lo[mt] = mn_lo; m_hi[mt] = mn_hi;

            const int pr = wid * 32 + mt * 16 + lq;
            #pragma unroll
            for (int nt = 0; nt < 8; nt++){
                float2 w0, w1;
                w0.x = __uint_as_float(f2tf(s[mt][nt][0]));
                w0.y = __uint_as_float(f2tf(s[mt][nt][1]));
                w1.x = __uint_as_float(f2tf(s[mt][nt][2]));
                w1.y = __uint_as_float(f2tf(s[mt][nt][3]));
                *(float2*)&Ps[(pr    ) * LDP + nt * 8 + lr * 2] = w0;
                *(float2*)&Ps[(pr + 8) * LDP + nt * 8 + lr * 2] = w1;
            }
        }
        __syncwarp();

        // ---- O += P @ V  (V^T fragments, shared across both m16 tiles) ----
        const int pr0 = wid * 32 + lq, pr1 = pr0 + 16;
        #pragma unroll
        for (int ks = 0; ks < 8; ks++){
            uint32_t af0[4], af1[4];
            af0[0] = __float_as_uint(Ps[(pr0    ) * LDP + ks * 8 + lr    ]);
            af0[1] = __float_as_uint(Ps[(pr0 + 8) * LDP + ks * 8 + lr    ]);
            af0[2] = __float_as_uint(Ps[(pr0    ) * LDP + ks * 8 + lr + 4]);
            af0[3] = __float_as_uint(Ps[(pr0 + 8) * LDP + ks * 8 + lr + 4]);
            af1[0] = __float_as_uint(Ps[(pr1    ) * LDP + ks * 8 + lr    ]);
            af1[1] = __float_as_uint(Ps[(pr1 + 8) * LDP + ks * 8 + lr    ]);
            af1[2] = __float_as_uint(Ps[(pr1    ) * LDP + ks * 8 + lr + 4]);
            af1[3] = __float_as_uint(Ps[(pr1 + 8) * LDP + ks * 8 + lr + 4]);
            #pragma unroll
            for (int nt = 0; nt < 8; nt++){
                uint32_t bf2[2];
                bf2[0] = __float_as_uint(vs_[(nt * 8 + lq) * LDP + ks * 8 + lr    ]);
                bf2[1] = __float_as_uint(vs_[(nt * 8 + lq) * LDP + ks * 8 + lr + 4]);
                mma_tf32(o[0][nt], af0, bf2);
                mma_tf32(o[1][nt], af1, bf2);
            }
        }
        __syncwarp();
    }

    // ---- epilogue: tf32(O / l) -> g_AO[b, n, h*64 + d] ----
    const int bidx = z / NHEAD, h = z - bidx * NHEAD;
    #pragma unroll
    for (int mt = 0; mt < 2; mt++){
        const float inv_lo = 1.f / l_lo[mt], inv_hi = 1.f / l_hi[mt];
        const int r = row0 + wid * 32 + mt * 16 + lq;
        float* ob = g_AO + ((size_t)(bidx * SEQ + r)) * EMB + h * HDIM;
        #pragma unroll
        for (int nt = 0; nt < 8; nt++){
            const int col = nt * 8 + lr * 2;
            float2 w0, w1;
            w0.x = __uint_as_float(f2tf(o[mt][nt][0] * inv_lo));
            w0.y = __uint_as_float(f2tf(o[mt][nt][1] * inv_lo));
            w1.x = __uint_as_float(f2tf(o[mt][nt][2] * inv_hi));
            w1.y = __uint_as_float(f2tf(o[mt][nt][3] * inv_hi));
            *(float2*)(ob + col)           = w0;
            *(float2*)(ob + 8 * EMB + col) = w1;
        }
    }
}

// ----------------------------------------------------------------------------
extern "C" void kernel_launch(void* const* d_in, const int* in_sizes, int n_in,
                              void* d_out, int out_size)
{
    const float* x      = (const float*)d_in[0];
    const float* w_qkv  = (const float*)d_in[1];
    const float* b_qkv  = (const float*)d_in[2];
    const float* w_proj = (const float*)d_in[3];
    const float* b_proj = (const float*)d_in[4];
    float* out = (float*)d_out;

    constexpr int ASMEM  = (4 * 64 * 68 + 128 * 68) * 4;   // 104448 B
    constexpr int MMSMEM = 2 * 2 * 128 * 36 * 4;           // 73728 B
    cudaFuncSetAttribute(attn_kernel,  cudaFuncAttributeMaxDynamicSharedMemorySize, ASMEM);
    cudaFuncSetAttribute(mm_kernel<0>, cudaFuncAttributeMaxDynamicSharedMemorySize, MMSMEM);
    cudaFuncSetAttribute(mm_kernel<3>, cudaFuncAttributeMaxDynamicSharedMemorySize, MMSMEM);

    // 0) pre-round all inputs to tf32, one launch
    constexpr int QTOT = Q1 + Q2 + Q3;            // 1376256 quads
    round_all_kernel<<<(QTOT + 255) / 256, 256>>>(x, w_qkv, w_proj);

    // 1) QKV GEMM + bias -> tf32-rounded Q(scaled)/K/V^T scratch
    mm_kernel<0><<<dim3(18, 32), 256, MMSMEM>>>(b_qkv, nullptr);
    // 2) fused flash attention -> g_AO (tf32-rounded)
    attn_kernel<<<dim3(SEQ / 128, BH), 128, ASMEM>>>();
    // 3) proj + bias -> out
    mm_kernel<3><<<dim3(6, 32), 256, MMSMEM>>>(b_proj, out);
}

// round 15
// speedup vs baseline: 1.1600x; 1.0130x over previous
#include <cuda_runtime.h>
#include <cstdint>

#define SEQ   2048
#define EMB   768
#define NHEAD 12
#define HDIM  64
#define BH    24          // batch * heads
#define MTOT  4096        // batch * seq

// ---------------- scratch (allocation-free), all stored tf32-rounded ----------------
__device__ float g_Qs[(size_t)BH*SEQ*HDIM];   // scaled Q  [bh, n, d]
__device__ float g_Kc[(size_t)BH*SEQ*HDIM];   // K         [bh, n, d]
__device__ float g_Vt[(size_t)BH*HDIM*SEQ];   // V^T       [bh, d, n]
__device__ float g_AO[(size_t)MTOT*EMB];      // attention out [b, n, c] (tf32-rounded)
__device__ float g_X [(size_t)MTOT*EMB];      // x rounded to tf32
__device__ float g_Wq[(size_t)3*EMB*EMB];     // w_qkv rounded to tf32
__device__ float g_Wp[(size_t)EMB*EMB];       // w_proj rounded to tf32

// ---------------- helpers ----------------
__device__ __forceinline__ uint32_t f2tf(float x){
    uint32_t r; asm("cvt.rna.tf32.f32 %0, %1;" : "=r"(r) : "f"(x)); return r;
}
__device__ __forceinline__ void cp16(uint32_t dst, const void* src){
    asm volatile("cp.async.cg.shared.global [%0], [%1], 16;" :: "r"(dst), "l"(src));
}
__device__ __forceinline__ void cp_commit(){
    asm volatile("cp.async.commit_group;" ::: "memory");
}
template<int N>
__device__ __forceinline__ void cp_wait(){
    asm volatile("cp.async.wait_group %0;" :: "n"(N) : "memory");
}
__device__ __forceinline__ void mma_tf32(float* c, const uint32_t* a, const uint32_t* b){
    asm volatile(
        "mma.sync.aligned.m16n8k8.row.col.f32.tf32.tf32.f32 "
        "{%0,%1,%2,%3}, {%4,%5,%6,%7}, {%8,%9}, {%0,%1,%2,%3};"
        : "+f"(c[0]), "+f"(c[1]), "+f"(c[2]), "+f"(c[3])
        : "r"(a[0]), "r"(a[1]), "r"(a[2]), "r"(a[3]), "r"(b[0]), "r"(b[1]));
}

// ----------------------------------------------------------------------------
// Fused tf32 pre-round of all three inputs in ONE launch.
// ----------------------------------------------------------------------------
#define Q1 (MTOT*EMB/4)
#define Q2 (3*EMB*EMB/4)
#define Q3 (EMB*EMB/4)
__global__ void __launch_bounds__(256) round_all_kernel(
    const float* __restrict__ x, const float* __restrict__ wq,
    const float* __restrict__ wp)
{
    int q = blockIdx.x * 256 + threadIdx.x;
    const float* src; float* dst; int off;
    if (q < Q1)           { src = x;  dst = g_X;  off = q; }
    else if (q < Q1 + Q2) { src = wq; dst = g_Wq; off = q - Q1; }
    else if (q < Q1 + Q2 + Q3) { src = wp; dst = g_Wp; off = q - Q1 - Q2; }
    else return;
    int i = off * 4;
    float4 v = *(const float4*)(src + i);
    v.x = __uint_as_float(f2tf(v.x));
    v.y = __uint_as_float(f2tf(v.y));
    v.z = __uint_as_float(f2tf(v.z));
    v.w = __uint_as_float(f2tf(v.w));
    *(float4*)(dst + i) = v;
}

// ----------------------------------------------------------------------------
// tf32 mma.sync GEMM: D[BM, 128] tile = A[M,K] @ B[N,K]^T + bias, BK=32.
// Single __syncthreads per k-iter. Warp layout: (BM/32) warps in M x rest in N.
//   MODE 0 (BM=128): QKV -> g_Qs(x0.125)/g_Kc/g_Vt (V transposed)
//   MODE 3 (BM=64) : proj -> Cout + bias   (3 CTAs/SM -> single full wave)
// ----------------------------------------------------------------------------
template<int MODE, int BM>
__global__ void __launch_bounds__(256, (BM == 128) ? 2 : 3) mm_kernel(
    const float* __restrict__ bias, float* __restrict__ Cout)
{
    constexpr int BN = 128, BK = 32, LDS = 36;
    constexpr int WM = BM / 32;           // warps along M (4 or 2)
    constexpr int WN = 8 / WM;            // warps along N (2 or 4)
    constexpr int WCOLS = BN / WN;        // cols per warp (64 or 32)
    constexpr int NT = WCOLS / 8;         // n8 tiles per warp (8 or 4)

    extern __shared__ float smg[];
    float* As = smg;                      // [2][BM*36]
    float* Bs = smg + 2 * BM * LDS;       // [2][128*36]

    const int tid  = threadIdx.x;
    const int wid  = tid >> 5, lane = tid & 31;
    const int lq   = lane >> 2, lr = lane & 3;
    const int mOff = (wid % WM) * 32;
    const int nOff = (wid / WM) * WCOLS;
    const int row0 = blockIdx.y * BM, col0 = blockIdx.x * BN;

    const float* Ap = (MODE == 0) ? g_X  : g_AO;
    const float* Bp = (MODE == 0) ? g_Wq : g_Wp;
    const int K = EMB;

    const uint32_t sA = (uint32_t)__cvta_generic_to_shared(As);
    const uint32_t sB = (uint32_t)__cvta_generic_to_shared(Bs);
    constexpr uint32_t ABUF = BM * LDS * 4;
    constexpr uint32_t BBUF = 128 * LDS * 4;

    auto load_tile = [&](int kt, int buf){
        const float* ag = Ap + (size_t)row0 * K + kt * BK;
        const uint32_t da = sA + buf * ABUF;
        #pragma unroll
        for (int i = 0; i < BM / 32; i++){        // BM x 32 f = BM*8 float4
            int ch = tid + i * 256, r = ch >> 3, c4 = ch & 7;
            cp16(da + (uint32_t)(r * LDS + c4 * 4) * 4, ag + (size_t)r * K + c4 * 4);
        }
        const float* bg = Bp + (size_t)col0 * K + kt * BK;
        const uint32_t db = sB + buf * BBUF;
        #pragma unroll
        for (int i = 0; i < 4; i++){
            int ch = tid + i * 256, r = ch >> 3, c4 = ch & 7;
            cp16(db + (uint32_t)(r * LDS + c4 * 4) * 4, bg + (size_t)r * K + c4 * 4);
        }
    };

    float acc[2][NT][4];
    #pragma unroll
    for (int mt = 0; mt < 2; mt++)
        #pragma unroll
        for (int nt = 0; nt < NT; nt++)
            #pragma unroll
            for (int j = 0; j < 4; j++) acc[mt][nt][j] = 0.f;

    load_tile(0, 0);
    cp_commit();

    const int KT = K / BK;                       // 24
    for (int kt = 0; kt < KT; kt++){
        cp_wait<0>();
        __syncthreads();                          // cp(kt) visible + buf^1 free
        if (kt + 1 < KT){ load_tile(kt + 1, (kt + 1) & 1); cp_commit(); }

        const float* a_s = As + (kt & 1) * BM * LDS;
        const float* b_s = Bs + (kt & 1) * 128 * LDS;
        #pragma unroll
        for (int s = 0; s < 4; s++){
            const int k0 = s * 8;
            uint32_t af[2][4];
            #pragma unroll
            for (int mt = 0; mt < 2; mt++){
                const int r = mOff + mt * 16 + lq;
                af[mt][0] = __float_as_uint(a_s[(r    ) * LDS + k0 + lr    ]);
                af[mt][1] = __float_as_uint(a_s[(r + 8) * LDS + k0 + lr    ]);
                af[mt][2] = __float_as_uint(a_s[(r    ) * LDS + k0 + lr + 4]);
                af[mt][3] = __float_as_uint(a_s[(r + 8) * LDS + k0 + lr + 4]);
            }
            uint32_t bf[NT][2];
            #pragma unroll
            for (int nt = 0; nt < NT; nt++){
                const int c = nOff + nt * 8 + lq;
                bf[nt][0] = __float_as_uint(b_s[c * LDS + k0 + lr    ]);
                bf[nt][1] = __float_as_uint(b_s[c * LDS + k0 + lr + 4]);
            }
            #pragma unroll
            for (int mt = 0; mt < 2; mt++)
                #pragma unroll
                for (int nt = 0; nt < NT; nt++)
                    mma_tf32(acc[mt][nt], af[mt], bf[nt]);
        }
    }

    // ---------------- epilogue ----------------
    #pragma unroll
    for (int mt = 0; mt < 2; mt++){
        const int r1 = row0 + mOff + mt * 16 + lq;
        #pragma unroll
        for (int nt = 0; nt < NT; nt++){
            const int col = col0 + nOff + nt * 8 + lr * 2;
            #pragma unroll
            for (int half = 0; half < 2; half++){
                const int r = r1 + half * 8;
                const float v0 = acc[mt][nt][half * 2], v1 = acc[mt][nt][half * 2 + 1];
                if (MODE == 0){
                    const int part = col / EMB, cc = col - part * EMB;
                    const int h = cc >> 6, d = cc & 63;
                    const int bidx = r >> 11, n = r & (SEQ - 1);
                    if (part < 2){
                        const float sc = (part == 0) ? 0.125f : 1.0f;
                        float* dst = (part == 0 ? g_Qs : g_Kc)
                                   + (((size_t)(bidx * NHEAD + h) * SEQ + n) * HDIM + d);
                        float2 w;
                        w.x = __uint_as_float(f2tf((v0 + bias[col    ]) * sc));
                        w.y = __uint_as_float(f2tf((v1 + bias[col + 1]) * sc));
                        *(float2*)dst = w;
                    } else {                     // V transposed: [bh, d, n]
                        const size_t vb = ((size_t)(bidx * NHEAD + h) * HDIM + d) * SEQ + n;
                        g_Vt[vb]       = __uint_as_float(f2tf(v0 + bias[col]));
                        g_Vt[vb + SEQ] = __uint_as_float(f2tf(v1 + bias[col + 1]));
                    }
                } else {
                    *(float2*)(Cout + (size_t)r * EMB + col)
                        = make_float2(v0 + bias[col], v1 + bias[col + 1]);
                }
            }
        }
    }
}

// ----------------------------------------------------------------------------
// Fused flash attention (champion config, byte-identical to R14):
// 4 warps x 32 query rows = 128 rows/CTA; S-phase nt-outer; LDP=68
// conflict-free; V^T tiles; 2 CTAs/SM.
// ----------------------------------------------------------------------------
__global__ void __launch_bounds__(128, 2) attn_kernel()
{
    constexpr int TILE = 64, LDP = 68, NKT = SEQ / TILE;
    extern __shared__ float sm[];
    float* Ks = sm;                       // [2][64*68]  K tile [key][d]
    float* Vs = sm + 2 * TILE * LDP;      // [2][64*68]  V^T tile [d][key]
    float* Ps = sm + 4 * TILE * LDP;      // [128*68]    Q staging, then P

    const int tid  = threadIdx.x;
    const int wid  = tid >> 5, lane = tid & 31;
    const int lq   = lane >> 2, lr = lane & 3;
    const int z    = blockIdx.y;                 // head index (bh)
    const int row0 = blockIdx.x * 128;
    const size_t base  = (size_t)z * SEQ * HDIM;

    {
        const float* qg = g_Qs + base + (size_t)row0 * HDIM;
        #pragma unroll
        for (int i = 0; i < 16; i++){
            int ch = tid + i * 128, r = ch >> 4, c4 = ch & 15;
            *(float4*)&Ps[r * LDP + c4 * 4] = *(const float4*)(qg + r * HDIM + c4 * 4);
        }
    }
    __syncthreads();
    uint32_t qf[2][8][4];
    #pragma unroll
    for (int mt = 0; mt < 2; mt++){
        const int r = wid * 32 + mt * 16 + lq;
        #pragma unroll
        for (int ks = 0; ks < 8; ks++){
            qf[mt][ks][0] = __float_as_uint(Ps[(r    ) * LDP + ks * 8 + lr    ]);
            qf[mt][ks][1] = __float_as_uint(Ps[(r + 8) * LDP + ks * 8 + lr    ]);
            qf[mt][ks][2] = __float_as_uint(Ps[(r    ) * LDP + ks * 8 + lr + 4]);
            qf[mt][ks][3] = __float_as_uint(Ps[(r + 8) * LDP + ks * 8 + lr + 4]);
        }
    }

    float o[2][8][4];
    #pragma unroll
    for (int mt = 0; mt < 2; mt++)
        #pragma unroll
        for (int nt = 0; nt < 8; nt++)
            #pragma unroll
            for (int j = 0; j < 4; j++) o[mt][nt][j] = 0.f;
    float m_lo[2] = {-1e30f, -1e30f}, m_hi[2] = {-1e30f, -1e30f};
    float l_lo[2] = {0.f, 0.f},       l_hi[2] = {0.f, 0.f};

    auto load_kv = [&](int kt, int buf){
        const float* kg = g_Kc + base + (size_t)(kt * TILE) * HDIM;   // [key][d]
        const float* vg = g_Vt + base + (size_t)(kt * TILE);          // [d][n]
        uint32_t kd = (uint32_t)__cvta_generic_to_shared(Ks + buf * TILE * LDP);
        uint32_t vd = (uint32_t)__cvta_generic_to_shared(Vs + buf * TILE * LDP);
        #pragma unroll
        for (int i = 0; i < 8; i++){              // 64x64 floats = 1024 float4
            int ch = tid + i * 128, r = ch >> 4, c4 = ch & 15;
            uint32_t off = (uint32_t)(r * LDP + c4 * 4) * 4;
            cp16(kd + off, kg + (size_t)r * HDIM + c4 * 4);
            cp16(vd + off, vg + (size_t)r * SEQ  + c4 * 4);
        }
    };

    load_kv(0, 0);
    cp_commit();

    for (int kt = 0; kt < NKT; kt++){
        const int buf = kt & 1;
        cp_wait<0>();
        __syncthreads();
        if (kt + 1 < NKT){ load_kv(kt + 1, buf ^ 1); cp_commit(); }

        const float* ks_ = Ks + buf * TILE * LDP;
        const float* vs_ = Vs + buf * TILE * LDP;

        float s[2][8][4];
        #pragma unroll
        for (int mt = 0; mt < 2; mt++)
            #pragma unroll
            for (int nt = 0; nt < 8; nt++)
                #pragma unroll
                for (int j = 0; j < 4; j++) s[mt][nt][j] = 0.f;
        #pragma unroll
        for (int nt = 0; nt < 8; nt++){
            uint32_t bfk[8][2];
            #pragma unroll
            for (int ks = 0; ks < 8; ks++){
                bfk[ks][0] = __float_as_uint(ks_[(nt * 8 + lq) * LDP + ks * 8 + lr    ]);
                bfk[ks][1] = __float_as_uint(ks_[(nt * 8 + lq) * LDP + ks * 8 + lr + 4]);
            }
            #pragma unroll
            for (int ks = 0; ks < 8; ks++){
                mma_tf32(s[0][nt], qf[0][ks], bfk[ks]);
                mma_tf32(s[1][nt], qf[1][ks], bfk[ks]);
            }
        }

        #pragma unroll
        for (int mt = 0; mt < 2; mt++){
            float mx_lo = -1e30f, mx_hi = -1e30f;
            #pragma unroll
            for (int nt = 0; nt < 8; nt++){
                mx_lo = fmaxf(mx_lo, fmaxf(s[mt][nt][0], s[mt][nt][1]));
                mx_hi = fmaxf(mx_hi, fmaxf(s[mt][nt][2], s[mt][nt][3]));
            }
            mx_lo = fmaxf(mx_lo, __shfl_xor_sync(~0u, mx_lo, 1));
            mx_lo = fmaxf(mx_lo, __shfl_xor_sync(~0u, mx_lo, 2));
            mx_hi = fmaxf(mx_hi, __shfl_xor_sync(~0u, mx_hi, 1));
            mx_hi = fmaxf(mx_hi, __shfl_xor_sync(~0u, mx_hi, 2));
            const float mn_lo = fmaxf(m_lo[mt], mx_lo), mn_hi = fmaxf(m_hi[mt], mx_hi);
            const float c_lo = __expf(m_lo[mt] - mn_lo), c_hi = __expf(m_hi[mt] - mn_hi);
            float sum_lo = 0.f, sum_hi = 0.f;
            #pragma unroll
            for (int nt = 0; nt < 8; nt++){
                s[mt][nt][0] = __expf(s[mt][nt][0] - mn_lo);
                s[mt][nt][1] = __expf(s[mt][nt][1] - mn_lo);
                s[mt][nt][2] = __expf(s[mt][nt][2] - mn_hi);
                s[mt][nt][3] = __expf(s[mt][nt][3] - mn_hi);
                sum_lo += s[mt][nt][0] + s[mt][nt][1];
                sum_hi += s[mt][nt][2] + s[mt][nt][3];
            }
            sum_lo += __shfl_xor_sync(~0u, sum_lo, 1);
            sum_lo += __shfl_xor_sync(~0u, sum_lo, 2);
            sum_hi += __shfl_xor_sync(~0u, sum_hi, 1);
            sum_hi += __shfl_xor_sync(~0u, sum_hi, 2);
            l_lo[mt] = l_lo[mt] * c_lo + sum_lo;
            l_hi[mt] = l_hi[mt] * c_hi + sum_hi;
            #pragma unroll
            for (int nt = 0; nt < 8; nt++){
                o[mt][nt][0] *= c_lo; o[mt][nt][1] *= c_lo;
                o[mt][nt][2] *= c_hi; o[mt][nt][3] *= c_hi;
            }
            m_lo[mt] = mn_lo; m_hi[mt] = mn_hi;

            const int pr = wid * 32 + mt * 16 + lq;
            #pragma unroll
            for (int nt = 0; nt < 8; nt++){
                float2 w0, w1;
                w0.x = __uint_as_float(f2tf(s[mt][nt][0]));
                w0.y = __uint_as_float(f2tf(s[mt][nt][1]));
                w1.x = __uint_as_float(f2tf(s[mt][nt][2]));
                w1.y = __uint_as_float(f2tf(s[mt][nt][3]));
                *(float2*)&Ps[(pr    ) * LDP + nt * 8 + lr * 2] = w0;
                *(float2*)&Ps[(pr + 8) * LDP + nt * 8 + lr * 2] = w1;
            }
        }
        __syncwarp();

        const int pr0 = wid * 32 + lq, pr1 = pr0 + 16;
        #pragma unroll
        for (int ks = 0; ks < 8; ks++){
            uint32_t af0[4], af1[4];
            af0[0] = __float_as_uint(Ps[(pr0    ) * LDP + ks * 8 + lr    ]);
            af0[1] = __float_as_uint(Ps[(pr0 + 8) * LDP + ks * 8 + lr    ]);
            af0[2] = __float_as_uint(Ps[(pr0    ) * LDP + ks * 8 + lr + 4]);
            af0[3] = __float_as_uint(Ps[(pr0 + 8) * LDP + ks * 8 + lr + 4]);
            af1[0] = __float_as_uint(Ps[(pr1    ) * LDP + ks * 8 + lr    ]);
            af1[1] = __float_as_uint(Ps[(pr1 + 8) * LDP + ks * 8 + lr    ]);
            af1[2] = __float_as_uint(Ps[(pr1    ) * LDP + ks * 8 + lr + 4]);
            af1[3] = __float_as_uint(Ps[(pr1 + 8) * LDP + ks * 8 + lr + 4]);
            #pragma unroll
            for (int nt = 0; nt < 8; nt++){
                uint32_t bf2[2];
                bf2[0] = __float_as_uint(vs_[(nt * 8 + lq) * LDP + ks * 8 + lr    ]);
                bf2[1] = __float_as_uint(vs_[(nt * 8 + lq) * LDP + ks * 8 + lr + 4]);
                mma_tf32(o[0][nt], af0, bf2);
                mma_tf32(o[1][nt], af1, bf2);
            }
        }
        __syncwarp();
    }

    const int bidx = z / NHEAD, h = z - bidx * NHEAD;
    #pragma unroll
    for (int mt = 0; mt < 2; mt++){
        const float inv_lo = 1.f / l_lo[mt], inv_hi = 1.f / l_hi[mt];
        const int r = row0 + wid * 32 + mt * 16 + lq;
        float* ob = g_AO + ((size_t)(bidx * SEQ + r)) * EMB + h * HDIM;
        #pragma unroll
        for (int nt = 0; nt < 8; nt++){
            const int col = nt * 8 + lr * 2;
            float2 w0, w1;
            w0.x = __uint_as_float(f2tf(o[mt][nt][0] * inv_lo));
            w0.y = __uint_as_float(f2tf(o[mt][nt][1] * inv_lo));
            w1.x = __uint_as_float(f2tf(o[mt][nt][2] * inv_hi));
            w1.y = __uint_as_float(f2tf(o[mt][nt][3] * inv_hi));
            *(float2*)(ob + col)           = w0;
            *(float2*)(ob + 8 * EMB + col) = w1;
        }
    }
}

// ----------------------------------------------------------------------------
extern "C" void kernel_launch(void* const* d_in, const int* in_sizes, int n_in,
                              void* d_out, int out_size)
{
    const float* x      = (const float*)d_in[0];
    const float* w_qkv  = (const float*)d_in[1];
    const float* b_qkv  = (const float*)d_in[2];
    const float* w_proj = (const float*)d_in[3];
    const float* b_proj = (const float*)d_in[4];
    float* out = (float*)d_out;

    constexpr int ASMEM   = (4 * 64 * 68 + 128 * 68) * 4;       // 104448 B
    constexpr int MMSMEM  = 2 * (128 + 128) * 36 * 4;           // 73728 B (BM=128)
    constexpr int MMSMEM64= 2 * (64 + 128) * 36 * 4;            // 55296 B (BM=64)
    cudaFuncSetAttribute(attn_kernel, cudaFuncAttributeMaxDynamicSharedMemorySize, ASMEM);
    cudaFuncSetAttribute((mm_kernel<0, 128>), cudaFuncAttributeMaxDynamicSharedMemorySize, MMSMEM);
    cudaFuncSetAttribute((mm_kernel<3, 64>),  cudaFuncAttributeMaxDynamicSharedMemorySize, MMSMEM64);

    // 0) pre-round all inputs to tf32, one launch
    constexpr int QTOT = Q1 + Q2 + Q3;
    round_all_kernel<<<(QTOT + 255) / 256, 256>>>(x, w_qkv, w_proj);

    // 1) QKV GEMM + bias -> tf32-rounded Q(scaled)/K/V^T scratch
    mm_kernel<0, 128><<<dim3(18, 32), 256, MMSMEM>>>(b_qkv, nullptr);
    // 2) fused flash attention -> g_AO (tf32-rounded)
    attn_kernel<<<dim3(SEQ / 128, BH), 128, ASMEM>>>();
    // 3) proj + bias -> out  (BM=64: 384 CTAs, 3 CTAs/SM -> single wave)
    mm_kernel<3, 64><<<dim3(6, 64), 256, MMSMEM64>>>(b_proj, out);
}